// round 7
// baseline (speedup 1.0000x reference)
#include <cuda_runtime.h>
#include <cstdint>

#define SEQ   2048
#define BATCH 128
#define INP   64
#define HID   256
#define GH    1024   // 4*HID
#define OUTD  64

typedef unsigned long long ull;

// packed 2xfp32 FMA (B300: FFMA-3reg is half rate; f32x2 restores full rate)
#define FMA2(d, a, b) asm("fma.rn.f32x2 %0, %1, %2, %0;" : "+l"(d) : "l"(a), "l"(b))

__device__ __forceinline__ float hsum2(ull v) {
    float2 f = *(float2*)&v;
    return f.x + f.y;
}

// ---------------- scratch (static device arrays; no cudaMalloc) --------
__device__ float g_xw[(size_t)SEQ * BATCH * GH];   // x @ W_ih^T + b
__device__ float g_hs[(size_t)SEQ * BATCH * HID];  // h history (streamed)

// =============================================================
// Kernel A (proven, ~940us): xw = x @ W_ih^T + b
// =============================================================
__global__ void __launch_bounds__(256) k_gemm_xw(const float* __restrict__ x,
                                                 const float* __restrict__ Wih,
                                                 const float* __restrict__ bias)
{
    extern __shared__ float4 smA[];
    float4* Xs = smA;            // 64 rows x 19
    float4* Ws = smA + 64 * 19;  // 128 rows x 19

    const int t  = threadIdx.x;
    const int m0 = blockIdx.x * 64;
    const int n0 = blockIdx.y * 128;

    const float4* x4 = (const float4*)x;
    const float4* w4 = (const float4*)Wih;

    #pragma unroll
    for (int idx = t; idx < 64 * 16; idx += 256) {
        int r = idx >> 4, c = idx & 15;
        Xs[r * 19 + c] = x4[(size_t)(m0 + r) * 16 + c];
    }
    #pragma unroll
    for (int idx = t; idx < 128 * 16; idx += 256) {
        int r = idx >> 4, c = idx & 15;
        Ws[r * 19 + c] = w4[(size_t)(n0 + r) * 16 + c];
    }
    __syncthreads();

    const int tx = t & 15, ty = t >> 4;
    float acc[4][8];
    #pragma unroll
    for (int i = 0; i < 4; i++)
        #pragma unroll
        for (int j = 0; j < 8; j++) acc[i][j] = 0.f;

    #pragma unroll
    for (int k4 = 0; k4 < 16; k4++) {
        float4 a[4], bv[8];
        #pragma unroll
        for (int i = 0; i < 4; i++) a[i] = Xs[(ty + 16 * i) * 19 + k4];
        #pragma unroll
        for (int j = 0; j < 8; j++) bv[j] = Ws[(tx + 16 * j) * 19 + k4];
        #pragma unroll
        for (int i = 0; i < 4; i++)
            #pragma unroll
            for (int j = 0; j < 8; j++)
                acc[i][j] += a[i].x * bv[j].x + a[i].y * bv[j].y +
                             a[i].z * bv[j].z + a[i].w * bv[j].w;
    }
    #pragma unroll
    for (int i = 0; i < 4; i++) {
        int m = m0 + ty + 16 * i;
        #pragma unroll
        for (int j = 0; j < 8; j++) {
            int n = n0 + tx + 16 * j;
            g_xw[(size_t)m * GH + n] = acc[i][j] + __ldg(&bias[n]);
        }
    }
}

// =============================================================
// Kernel B: persistent LSTM scan — push-based DSMEM pipeline.
// 128 CTAs = 16 bgroups(8 b) x 8 ugroups(32 u). Cluster of 8.
// Thread = (u 0..31, b2 0..3, ks 0..3): computes all 4 gates of
// unit u for 2 batches (ks selects K-quarter; after butterfly
// reduce every lane has all sums; lane pair covers batch lo/hi).
// h exchanged via st.async.shared::cluster + mbarrier complete_tx.
// No threadfence, no global atomics, no cluster.sync in the loop.
// =============================================================
#define WS2  272   // W row stride (floats): 4*KSK, and mod 32 == 16
#define KSK  68    // ks-slice skew (mod 32 == 4)
#define HSK  548   // H ks-slice stride (mod 32 == 4)
#define HBUF (4 * HSK)               // 2192 floats per H buffer

#define SM_W   0
#define SM_H   (128 * WS2)           // 34816 floats
#define SM_MB  (SM_H + 2 * HBUF)     // 39200 floats (mbar: 2 x u64)
#define SM_TOTB ((SM_MB + 4) * 4)    // 156816 bytes

__global__ void __launch_bounds__(512, 1) __cluster_dims__(8, 1, 1)
k_lstm(const float* __restrict__ h0, const float* __restrict__ c0,
       const float* __restrict__ Whh)
{
    extern __shared__ float smR[];
    float* Wsm = smR + SM_W;    // [row 0..127][ks*KSK + k]
    float* Hsm = smR + SM_H;    // [par][ks][b*KSK + k]

    const int t     = threadIdx.x;
    const int bgrp  = blockIdx.x >> 3;   // 0..15
    const int urank = blockIdx.x & 7;    // cluster rank
    const int b0g   = bgrp << 3;
    const int u0    = urank << 5;

    const int u  = t >> 4;        // 0..31 (unit)
    const int b2 = (t >> 2) & 3;  // 0..3 (batch pair)
    const int ks = t & 3;         // K quarter (lane bits 0-1)

    const uint32_t smem_base = (uint32_t)__cvta_generic_to_shared(smR);
    const uint32_t mbar_addr = smem_base + SM_MB * 4;

    // ---- mbarrier init + initial expect_tx (before cluster sync) ----
    if (t == 0) {
        asm volatile("mbarrier.init.shared.b64 [%0], 1;" :: "r"(mbar_addr) : "memory");
        asm volatile("mbarrier.init.shared.b64 [%0], 1;" :: "r"(mbar_addr + 8) : "memory");
        asm volatile("mbarrier.arrive.expect_tx.shared.b64 _, [%0], 8192;"
                     :: "r"(mbar_addr) : "memory");
        asm volatile("mbarrier.arrive.expect_tx.shared.b64 _, [%0], 8192;"
                     :: "r"(mbar_addr + 8) : "memory");
    }

    // ---- load W_hh slice into SMEM (skewed, conflict-free) ----
    for (int idx = t; idx < 128 * 64; idx += 512) {
        int r = idx >> 6, c4 = idx & 63;
        int grow = ((r >> 5) << 8) + u0 + (r & 31);
        float4 v = ((const float4*)Whh)[(size_t)grow * 64 + c4];
        int kss = c4 >> 4, kk = (c4 & 15) << 2;
        *(float4*)(Wsm + r * WS2 + kss * KSK + kk) = v;
    }
    // ---- init H[0] with full h0 for my 8 batches ----
    {
        int b = t >> 6, c4 = t & 63;
        float4 v = ((const float4*)h0)[(size_t)(b0g + b) * 64 + c4];
        int kss = c4 >> 4, kk = (c4 & 15) << 2;
        *(float4*)(Hsm + kss * HSK + b * KSK + kk) = v;
    }

    const int bsel = 2 * b2 + (ks >> 1);   // which batch this lane finalizes
    const int ug   = u0 + u;               // global unit
    float creg = c0[(size_t)(b0g + bsel) * HID + ug];

    __syncthreads();
    // cluster-wide: mbarriers + W + H0 visible before any st.async
    asm volatile("barrier.cluster.arrive.aligned;" ::: "memory");
    asm volatile("barrier.cluster.wait.aligned;"   ::: "memory");

    // ---- precompute remote smem bases for all 8 ranks ----
    uint32_t rbase[8];
    #pragma unroll
    for (int p = 0; p < 8; p++)
        asm("mapa.shared::cluster.u32 %0, %1, %2;"
            : "=r"(rbase[p]) : "r"(smem_base), "r"(p));

    const float* Wr0 = Wsm + (0 * 32 + u) * WS2 + ks * KSK;
    const float* Wr1 = Wsm + (1 * 32 + u) * WS2 + ks * KSK;
    const float* Wr2 = Wsm + (2 * 32 + u) * WS2 + ks * KSK;
    const float* Wr3 = Wsm + (3 * 32 + u) * WS2 + ks * KSK;

    // xw prefetch for step 0
    float xg0, xg1, xg2, xg3;
    {
        const float* xwp = g_xw + (size_t)(b0g + bsel) * GH + ug;
        xg0 = xwp[0]; xg1 = xwp[256]; xg2 = xwp[512]; xg3 = xwp[768];
    }

    const uint32_t hoff_const = (uint32_t)(SM_H) * 4 +
        (uint32_t)(((ug >> 6) * HSK) + bsel * KSK + (ug & 63)) * 4;

    #pragma unroll 1
    for (int step = 0; step < SEQ; step++) {
        const int par = step & 1, tb = par ^ 1;
        const float* Hb = Hsm + par * HBUF + ks * HSK + (2 * b2) * KSK;

        // ---- GEMV: 4 gate rows x 2 batches x 64-K-quarter ----
        ull a00 = 0, a10 = 0, a20 = 0, a30 = 0;   // batch lo
        ull a01 = 0, a11 = 0, a21 = 0, a31 = 0;   // batch hi
        #pragma unroll
        for (int k4 = 0; k4 < 16; k4++) {
            ulonglong2 hlo = *(const ulonglong2*)(Hb + k4 * 4);
            ulonglong2 hhi = *(const ulonglong2*)(Hb + KSK + k4 * 4);
            ulonglong2 w0 = *(const ulonglong2*)(Wr0 + k4 * 4);
            FMA2(a00, w0.x, hlo.x); FMA2(a00, w0.y, hlo.y);
            FMA2(a01, w0.x, hhi.x); FMA2(a01, w0.y, hhi.y);
            ulonglong2 w1 = *(const ulonglong2*)(Wr1 + k4 * 4);
            FMA2(a10, w1.x, hlo.x); FMA2(a10, w1.y, hlo.y);
            FMA2(a11, w1.x, hhi.x); FMA2(a11, w1.y, hhi.y);
            ulonglong2 w2 = *(const ulonglong2*)(Wr2 + k4 * 4);
            FMA2(a20, w2.x, hlo.x); FMA2(a20, w2.y, hlo.y);
            FMA2(a21, w2.x, hhi.x); FMA2(a21, w2.y, hhi.y);
            ulonglong2 w3 = *(const ulonglong2*)(Wr3 + k4 * 4);
            FMA2(a30, w3.x, hlo.x); FMA2(a30, w3.y, hlo.y);
            FMA2(a31, w3.x, hhi.x); FMA2(a31, w3.y, hhi.y);
        }

        // ---- butterfly reduce over ks (lane bits 0-1): all lanes get sums ----
        float s00 = hsum2(a00), s10 = hsum2(a10), s20 = hsum2(a20), s30 = hsum2(a30);
        float s01 = hsum2(a01), s11 = hsum2(a11), s21 = hsum2(a21), s31 = hsum2(a31);
        s00 += __shfl_xor_sync(~0u, s00, 1); s00 += __shfl_xor_sync(~0u, s00, 2);
        s10 += __shfl_xor_sync(~0u, s10, 1); s10 += __shfl_xor_sync(~0u, s10, 2);
        s20 += __shfl_xor_sync(~0u, s20, 1); s20 += __shfl_xor_sync(~0u, s20, 2);
        s30 += __shfl_xor_sync(~0u, s30, 1); s30 += __shfl_xor_sync(~0u, s30, 2);
        s01 += __shfl_xor_sync(~0u, s01, 1); s01 += __shfl_xor_sync(~0u, s01, 2);
        s11 += __shfl_xor_sync(~0u, s11, 1); s11 += __shfl_xor_sync(~0u, s11, 2);
        s21 += __shfl_xor_sync(~0u, s21, 1); s21 += __shfl_xor_sync(~0u, s21, 2);
        s31 += __shfl_xor_sync(~0u, s31, 1); s31 += __shfl_xor_sync(~0u, s31, 2);

        // ---- gate math for this lane's batch (bsel) ----
        const bool hi = (ks >= 2);
        float li = (hi ? s01 : s00) + xg0;
        float lf = (hi ? s11 : s10) + xg1;
        float lg = (hi ? s21 : s20) + xg2;
        float lo = (hi ? s31 : s30) + xg3;
        float ig = 1.f / (1.f + __expf(-li));
        float fg = 1.f / (1.f + __expf(-lf));
        float gg = tanhf(lg);
        float og = 1.f / (1.f + __expf(-lo));
        creg = fg * creg + ig * gg;
        float hh = og * tanhf(creg);

        // ---- history store (one lane of the duplicate pair) ----
        if ((ks & 1) == 0)
            __stcs(&g_hs[((size_t)step * BATCH + b0g + bsel) * HID + ug], hh);

        // ---- prefetch next step's xw (hidden behind push+wait) ----
        if (step + 1 < SEQ) {
            const float* xwp = g_xw + ((size_t)(step + 1) * BATCH + b0g + bsel) * GH + ug;
            xg0 = xwp[0]; xg1 = xwp[256]; xg2 = xwp[512]; xg3 = xwp[768];
        }

        if (step + 1 < SEQ) {
            // ---- push h to 4 ranks (lane pair covers all 8) ----
            const uint32_t hoff = hoff_const + (uint32_t)(tb * HBUF) * 4;
            const uint32_t mboff = (uint32_t)(SM_MB * 4 + tb * 8);
            const uint32_t hv = __float_as_uint(hh);
            const int rk = (ks & 1) << 2;
            #pragma unroll
            for (int j = 0; j < 4; j++) {
                uint32_t ra = rbase[rk + j] + hoff;
                uint32_t rm = rbase[rk + j] + mboff;
                asm volatile(
                    "st.async.shared::cluster.mbarrier::complete_tx::bytes.b32 [%0], %1, [%2];"
                    :: "r"(ra), "r"(hv), "r"(rm) : "memory");
            }

            // ---- wait for all 8KB of next h, then repost expect_tx ----
            const uint32_t mb = mbar_addr + tb * 8;
            const uint32_t ph = (step >> 1) & 1;
            asm volatile(
                "{\n\t.reg .pred P;\n"
                "WAITLP%=:\n\t"
                "mbarrier.try_wait.parity.acquire.cluster.shared::cta.b64 P, [%0], %1;\n\t"
                "@!P bra WAITLP%=;\n\t}"
                :: "r"(mb), "r"(ph) : "memory");
            if (t == 0)
                asm volatile("mbarrier.arrive.expect_tx.shared.b64 _, [%0], 8192;"
                             :: "r"(mb) : "memory");
            __syncthreads();   // repost ordered before anyone's next-step pushes
        }
    }
}

// =============================================================
// Kernel C: out = hs @ W_out^T + b_out. M=262144, N=64, K=256.
// =============================================================
__global__ void __launch_bounds__(256) k_gemm_out(const float* __restrict__ Wout,
                                                  const float* __restrict__ bout,
                                                  float* __restrict__ out)
{
    extern __shared__ ulonglong2 smC[];
    ulonglong2* Hs = smC;            // 64 x 19
    ulonglong2* Ws = smC + 64 * 19;  // 64 x 19

    const int t  = threadIdx.x;
    const int m0 = blockIdx.x * 64;
    const int tx = t & 15, ty = t >> 4;

    ull acc[4][4];
    #pragma unroll
    for (int i = 0; i < 4; i++)
        #pragma unroll
        for (int j = 0; j < 4; j++) acc[i][j] = 0ull;

    const ulonglong2* hs4 = (const ulonglong2*)g_hs;
    const ulonglong2* wo4 = (const ulonglong2*)Wout;

    for (int kc = 0; kc < 4; kc++) {
        __syncthreads();
        #pragma unroll
        for (int idx = t; idx < 64 * 16; idx += 256) {
            int rr = idx >> 4, c = idx & 15;
            Hs[rr * 19 + c] = hs4[(size_t)(m0 + rr) * 64 + kc * 16 + c];
            Ws[rr * 19 + c] = wo4[(size_t)rr * 64 + kc * 16 + c];
        }
        __syncthreads();
        #pragma unroll
        for (int k4 = 0; k4 < 16; k4++) {
            ulonglong2 a2[4];
            #pragma unroll
            for (int i = 0; i < 4; i++) a2[i] = Hs[(ty + 16 * i) * 19 + k4];
            #pragma unroll
            for (int j = 0; j < 4; j++) {
                ulonglong2 b2 = Ws[(tx + 16 * j) * 19 + k4];
                #pragma unroll
                for (int i = 0; i < 4; i++) {
                    FMA2(acc[i][j], a2[i].x, b2.x);
                    FMA2(acc[i][j], a2[i].y, b2.y);
                }
            }
        }
    }
    #pragma unroll
    for (int i = 0; i < 4; i++) {
        size_t m = (size_t)(m0 + ty + 16 * i);
        #pragma unroll
        for (int j = 0; j < 4; j++) {
            int n = tx + 16 * j;
            out[m * OUTD + n] = hsum2(acc[i][j]) + __ldg(&bout[n]);
        }
    }
}

// =============================================================
extern "C" void kernel_launch(void* const* d_in, const int* in_sizes, int n_in,
                              void* d_out, int out_size)
{
    (void)in_sizes; (void)n_in; (void)out_size;
    const float* x    = (const float*)d_in[0];
    const float* h0   = (const float*)d_in[1];
    const float* c0   = (const float*)d_in[2];
    const float* Wih  = (const float*)d_in[3];
    const float* Whh  = (const float*)d_in[4];
    const float* b    = (const float*)d_in[5];
    const float* Wout = (const float*)d_in[6];
    const float* bout = (const float*)d_in[7];
    float* out = (float*)d_out;

    const int smA = (64 + 128) * 19 * 16;   // 58368 B
    const int smB = SM_TOTB;                // 156816 B
    const int smC = (64 + 64) * 19 * 16;    // 38912 B

    cudaFuncSetAttribute(k_gemm_xw,  cudaFuncAttributeMaxDynamicSharedMemorySize, smA);
    cudaFuncSetAttribute(k_lstm,     cudaFuncAttributeMaxDynamicSharedMemorySize, smB);
    cudaFuncSetAttribute(k_gemm_out, cudaFuncAttributeMaxDynamicSharedMemorySize, smC);

    dim3 gridA((SEQ * BATCH) / 64, GH / 128);
    k_gemm_xw<<<gridA, 256, smA>>>(x, Wih, b);

    k_lstm<<<128, 512, smB>>>(h0, c0, Whh);

    k_gemm_out<<<(SEQ * BATCH) / 64, 256, smC>>>(Wout, bout, out);
}

// round 8
// speedup vs baseline: 1.6150x; 1.6150x over previous
#include <cuda_runtime.h>
#include <cstdint>

#define SEQ   2048
#define BATCH 128
#define INP   64
#define HID   256
#define GH    1024   // 4*HID
#define OUTD  64
#define NBG   16     // batch groups (8 batches each)
#define NUG   8      // unit groups  (32 units each)

typedef unsigned long long ull;

// packed 2xfp32 FMA (B300: FFMA-3reg is half rate; f32x2 restores full rate)
#define FMA2(d, a, b) asm("fma.rn.f32x2 %0, %1, %2, %0;" : "+l"(d) : "l"(a), "l"(b))

__device__ __forceinline__ float hsum2(ull v) {
    float2 f = *(float2*)&v;
    return f.x + f.y;
}

// ---------------- scratch (static device arrays; no cudaMalloc) --------
__device__ float g_hs[(size_t)SEQ * BATCH * HID];  // h history (streamed)
__device__ float g_hx[2][BATCH * HID];             // hot h exchange (L2)
__device__ unsigned g_cnt2[NBG * 32];              // per-bgroup counters (128B apart)
__device__ volatile unsigned g_gen2[NBG * 32];     // per-bgroup generations

// =============================================================
// Kernel B: persistent fused LSTM scan (xw GEMM fused in).
// 128 CTAs = 16 bgroups(8 b) x 8 ugroups(32 u / 128 gate rows).
// W_hh slice (134KB) + W_ih slice (42KB) resident in SMEM.
// x[t] double-buffered in SMEM, prefetched 2 steps ahead.
// Sync: per-bgroup (8 CTAs) atomic counter + generation in L2,
// exchange via compact double-buffered g_hx (R6-proven).
// =============================================================
#define WS   268   // W_hh row stride (floats) = 3*KSK + 64
#define KSK  68    // W_hh/H ks-slice skew
#define HSK  548   // H ks-slice stride = 8*68 + 4
#define LST  132   // L batch stride
#define WXS  84    // W_ih row stride (floats): 4 slices of 20 + 4 pad
#define KSX  20    // W_ih/x ks-slice skew (16 + 4)
#define XSK  164   // x ks-slice stride = 8*20 + 4
#define XBUF (4 * XSK)   // 656 floats per x buffer

#define SM_W    0
#define SM_WX   (128 * WS)             // 34304
#define SM_H    (SM_WX + 128 * WXS)    // 45056
#define SM_L    (SM_H + 4 * HSK)       // 47248
#define SM_X    (SM_L + 8 * LST)       // 48304
#define SM_TOT  (SM_X + 2 * XBUF)      // 49616 floats = 198464 B

__global__ void __launch_bounds__(512, 1)
k_lstm(const float* __restrict__ x, const float* __restrict__ h0,
       const float* __restrict__ c0, const float* __restrict__ Whh,
       const float* __restrict__ Wih, const float* __restrict__ bias)
{
    extern __shared__ float smR[];
    float* Wsm  = smR + SM_W;    // W_hh [row 0..127][ks*68 + k]
    float* Wxsm = smR + SM_WX;   // W_ih [row 0..127][ks*20 + k]
    float* Hsm  = smR + SM_H;    // h    [ks][b*68 + k]
    float* Lsm  = smR + SM_L;    // lin  [b][row]
    float* Xsm  = smR + SM_X;    // x    [par][ks][b*20 + k]

    const int t     = threadIdx.x;
    const int bgrp  = blockIdx.x >> 3;      // 0..15
    const int urank = blockIdx.x & 7;       // 0..7
    const int b0g   = bgrp << 3;            // global batch base
    const int u0    = urank << 5;           // global unit base

    const int w    = t >> 5, lane = t & 31;
    const int rp   = (w << 2) + (lane >> 3);     // row pair 0..63
    const int ks   = (lane >> 1) & 3;            // K quarter
    const int bp   = lane & 1;                   // batch half

    // ---- load W_hh slice into SMEM once (R5/R6-proven layout) ----
    for (int idx = t; idx < 128 * 64; idx += 512) {
        int r = idx >> 6, c4 = idx & 63;
        int grow = ((r >> 5) << 8) + u0 + (r & 31);
        float4 v = ((const float4*)Whh)[(size_t)grow * 64 + c4];
        int kss = c4 >> 4, kk = (c4 & 15) << 2;
        *(float4*)(Wsm + r * WS + kss * KSK + kk) = v;
    }
    // ---- load W_ih slice into SMEM once ----
    for (int idx = t; idx < 128 * 16; idx += 512) {
        int r = idx >> 4, c4 = idx & 15;       // c4 = float4 idx in 64-row
        int grow = ((r >> 5) << 8) + u0 + (r & 31);
        float4 v = ((const float4*)Wih)[(size_t)grow * 16 + c4];
        int kss = c4 >> 2, kk = (c4 & 3) << 2;
        *(float4*)(Wxsm + r * WXS + kss * KSX + kk) = v;
    }
    // ---- init Hsm from h0 ----
    {
        int b = t >> 6, c4 = t & 63;
        float4 v = ((const float4*)h0)[(size_t)(b0g + b) * 64 + c4];
        int kss = c4 >> 4, kk = (c4 & 15) << 2;
        *(float4*)(Hsm + kss * HSK + b * KSK + kk) = v;
    }
    // ---- init Xsm[0] from x[0]; prefetch x[1] into regs ----
    float4 xr = make_float4(0.f, 0.f, 0.f, 0.f);
    if (t < 128) {
        int b = t >> 4, c4 = t & 15;
        float4 v = ((const float4*)x)[(size_t)(b0g + b) * 16 + c4];
        int kss = c4 >> 2, kk = (c4 & 3) << 2;
        *(float4*)(Xsm + kss * XSK + b * KSX + kk) = v;
        xr = ((const float4*)x)[(size_t)(BATCH + b0g + b) * 16 + c4];
    }

    // ---- gate-thread state (t < 256) ----
    const int gb = t >> 5;
    const int gu = t & 31;
    const int ugt = u0 + gu;
    float creg = 0.f, bi = 0.f, bf = 0.f, bg = 0.f, bo = 0.f;
    if (t < 256) {
        creg = c0[(size_t)(b0g + gb) * HID + ugt];
        bi = bias[0 * HID + ugt];
        bf = bias[1 * HID + ugt];
        bg = bias[2 * HID + ugt];
        bo = bias[3 * HID + ugt];
    }

    __syncthreads();

    const float* Wp0  = Wsm  + (rp * 2 + 0) * WS  + ks * KSK;
    const float* Wp1  = Wsm  + (rp * 2 + 1) * WS  + ks * KSK;
    const float* Hp   = Hsm  + ks * HSK + (bp << 2) * KSK;
    const float* Wxp0 = Wxsm + (rp * 2 + 0) * WXS + ks * KSX;
    const float* Wxp1 = Wxsm + (rp * 2 + 1) * WXS + ks * KSX;

    unsigned* cntp = &g_cnt2[bgrp * 32];
    volatile unsigned* genp = &g_gen2[bgrp * 32];

    #pragma unroll 1
    for (int step = 0; step < SEQ; step++) {
        const int par = step & 1;

        // ---- fused GEMV: [h(256) | x(64)] x [W_hh | W_ih], 2 rows x 4 batches ----
        ull acc00 = 0, acc01 = 0, acc02 = 0, acc03 = 0;
        ull acc10 = 0, acc11 = 0, acc12 = 0, acc13 = 0;
        #pragma unroll
        for (int k4 = 0; k4 < 16; k4++) {
            ulonglong2 w0 = *(const ulonglong2*)(Wp0 + k4 * 4);
            ulonglong2 w1 = *(const ulonglong2*)(Wp1 + k4 * 4);
            ulonglong2 hv;
            hv = *(const ulonglong2*)(Hp + 0 * KSK + k4 * 4);
            FMA2(acc00, w0.x, hv.x); FMA2(acc00, w0.y, hv.y);
            FMA2(acc10, w1.x, hv.x); FMA2(acc10, w1.y, hv.y);
            hv = *(const ulonglong2*)(Hp + 1 * KSK + k4 * 4);
            FMA2(acc01, w0.x, hv.x); FMA2(acc01, w0.y, hv.y);
            FMA2(acc11, w1.x, hv.x); FMA2(acc11, w1.y, hv.y);
            hv = *(const ulonglong2*)(Hp + 2 * KSK + k4 * 4);
            FMA2(acc02, w0.x, hv.x); FMA2(acc02, w0.y, hv.y);
            FMA2(acc12, w1.x, hv.x); FMA2(acc12, w1.y, hv.y);
            hv = *(const ulonglong2*)(Hp + 3 * KSK + k4 * 4);
            FMA2(acc03, w0.x, hv.x); FMA2(acc03, w0.y, hv.y);
            FMA2(acc13, w1.x, hv.x); FMA2(acc13, w1.y, hv.y);
        }
        // x part (K=64, quarter of 16 per ks lane)
        {
            const float* Xq = Xsm + par * XBUF + ks * XSK + (bp << 2) * KSX;
            #pragma unroll
            for (int kx = 0; kx < 4; kx++) {
                ulonglong2 w0 = *(const ulonglong2*)(Wxp0 + kx * 4);
                ulonglong2 w1 = *(const ulonglong2*)(Wxp1 + kx * 4);
                ulonglong2 hv;
                hv = *(const ulonglong2*)(Xq + 0 * KSX + kx * 4);
                FMA2(acc00, w0.x, hv.x); FMA2(acc00, w0.y, hv.y);
                FMA2(acc10, w1.x, hv.x); FMA2(acc10, w1.y, hv.y);
                hv = *(const ulonglong2*)(Xq + 1 * KSX + kx * 4);
                FMA2(acc01, w0.x, hv.x); FMA2(acc01, w0.y, hv.y);
                FMA2(acc11, w1.x, hv.x); FMA2(acc11, w1.y, hv.y);
                hv = *(const ulonglong2*)(Xq + 2 * KSX + kx * 4);
                FMA2(acc02, w0.x, hv.x); FMA2(acc02, w0.y, hv.y);
                FMA2(acc12, w1.x, hv.x); FMA2(acc12, w1.y, hv.y);
                hv = *(const ulonglong2*)(Xq + 3 * KSX + kx * 4);
                FMA2(acc03, w0.x, hv.x); FMA2(acc03, w0.y, hv.y);
                FMA2(acc13, w1.x, hv.x); FMA2(acc13, w1.y, hv.y);
            }
        }
        // reduce over the 4 ks lanes (lane bits 1-2) and store to Lsm
        {
            const int r0 = rp * 2, bb = bp << 2;
            float v;
            v = hsum2(acc00); v += __shfl_xor_sync(~0u, v, 2); v += __shfl_xor_sync(~0u, v, 4);
            if (ks == 0) Lsm[(bb + 0) * LST + r0] = v;
            v = hsum2(acc01); v += __shfl_xor_sync(~0u, v, 2); v += __shfl_xor_sync(~0u, v, 4);
            if (ks == 0) Lsm[(bb + 1) * LST + r0] = v;
            v = hsum2(acc02); v += __shfl_xor_sync(~0u, v, 2); v += __shfl_xor_sync(~0u, v, 4);
            if (ks == 0) Lsm[(bb + 2) * LST + r0] = v;
            v = hsum2(acc03); v += __shfl_xor_sync(~0u, v, 2); v += __shfl_xor_sync(~0u, v, 4);
            if (ks == 0) Lsm[(bb + 3) * LST + r0] = v;
            v = hsum2(acc10); v += __shfl_xor_sync(~0u, v, 2); v += __shfl_xor_sync(~0u, v, 4);
            if (ks == 0) Lsm[(bb + 0) * LST + r0 + 1] = v;
            v = hsum2(acc11); v += __shfl_xor_sync(~0u, v, 2); v += __shfl_xor_sync(~0u, v, 4);
            if (ks == 0) Lsm[(bb + 1) * LST + r0 + 1] = v;
            v = hsum2(acc12); v += __shfl_xor_sync(~0u, v, 2); v += __shfl_xor_sync(~0u, v, 4);
            if (ks == 0) Lsm[(bb + 2) * LST + r0 + 1] = v;
            v = hsum2(acc13); v += __shfl_xor_sync(~0u, v, 2); v += __shfl_xor_sync(~0u, v, 4);
            if (ks == 0) Lsm[(bb + 3) * LST + r0 + 1] = v;
        }
        __syncthreads();

        // ---- gate update (t < 256) ----
        if (t < 256) {
            const float* Lb = Lsm + gb * LST;
            float iv = Lb[gu]      + bi;
            float fv = Lb[32 + gu] + bf;
            float gv = Lb[64 + gu] + bg;
            float ov = Lb[96 + gu] + bo;
            float ig = 1.f / (1.f + __expf(-iv));
            float fg = 1.f / (1.f + __expf(-fv));
            float gg = tanhf(gv);
            float og = 1.f / (1.f + __expf(-ov));
            float cc = fg * creg + ig * gg;
            creg = cc;
            float hh = og * tanhf(cc);
            g_hx[par][(b0g + gb) * HID + ugt] = hh;                 // hot exchange
            __stcs(&g_hs[((size_t)step * BATCH + b0g + gb) * HID + ugt], hh); // history
            __threadfence();
        }

        // ---- x pipeline: store x[step+1] to Xsm[par^1], prefetch x[step+2] ----
        if (t < 128 && step + 1 < SEQ) {
            int b = t >> 4, c4 = t & 15;
            int kss = c4 >> 2, kk = (c4 & 3) << 2;
            *(float4*)(Xsm + (par ^ 1) * XBUF + kss * XSK + b * KSX + kk) = xr;
            if (step + 2 < SEQ)
                xr = ((const float4*)x)[(size_t)((step + 2) * BATCH + b0g + b) * 16 + c4];
        }
        __syncthreads();

        // ---- per-bgroup barrier (8 CTAs), t==0 only ----
        if (t == 0) {
            unsigned cur = *genp;
            if (atomicAdd(cntp, 1u) == (unsigned)(NUG - 1)) {
                atomicExch(cntp, 0u);
                __threadfence();
                *genp = cur + 1u;
            } else {
                while (*genp == cur) { }
            }
            __threadfence();
        }
        __syncthreads();

        // ---- reload all 8 h slices for my 8 batches from g_hx[par] ----
        if (step < SEQ - 1) {
            int b = t >> 6, c4 = t & 63;
            float4 v = *(const float4*)&g_hx[par][(b0g + b) * HID + (c4 << 2)];
            int kss = c4 >> 4, kk = (c4 & 15) << 2;
            *(float4*)(Hsm + kss * HSK + b * KSK + kk) = v;
            __syncthreads();
        }
    }
}

// =============================================================
// Kernel C: out = hs @ W_out^T + b_out. M=262144, N=64, K=256.
// =============================================================
__global__ void __launch_bounds__(256) k_gemm_out(const float* __restrict__ Wout,
                                                  const float* __restrict__ bout,
                                                  float* __restrict__ out)
{
    extern __shared__ ulonglong2 smC[];
    ulonglong2* Hs = smC;            // 64 x 19
    ulonglong2* Ws = smC + 64 * 19;  // 64 x 19

    const int t  = threadIdx.x;
    const int m0 = blockIdx.x * 64;
    const int tx = t & 15, ty = t >> 4;

    ull acc[4][4];
    #pragma unroll
    for (int i = 0; i < 4; i++)
        #pragma unroll
        for (int j = 0; j < 4; j++) acc[i][j] = 0ull;

    const ulonglong2* hs4 = (const ulonglong2*)g_hs;
    const ulonglong2* wo4 = (const ulonglong2*)Wout;

    for (int kc = 0; kc < 4; kc++) {
        __syncthreads();
        #pragma unroll
        for (int idx = t; idx < 64 * 16; idx += 256) {
            int rr = idx >> 4, c = idx & 15;
            Hs[rr * 19 + c] = hs4[(size_t)(m0 + rr) * 64 + kc * 16 + c];
            Ws[rr * 19 + c] = wo4[(size_t)rr * 64 + kc * 16 + c];
        }
        __syncthreads();
        #pragma unroll
        for (int k4 = 0; k4 < 16; k4++) {
            ulonglong2 a2[4];
            #pragma unroll
            for (int i = 0; i < 4; i++) a2[i] = Hs[(ty + 16 * i) * 19 + k4];
            #pragma unroll
            for (int j = 0; j < 4; j++) {
                ulonglong2 b2 = Ws[(tx + 16 * j) * 19 + k4];
                #pragma unroll
                for (int i = 0; i < 4; i++) {
                    FMA2(acc[i][j], a2[i].x, b2.x);
                    FMA2(acc[i][j], a2[i].y, b2.y);
                }
            }
        }
    }
    #pragma unroll
    for (int i = 0; i < 4; i++) {
        size_t m = (size_t)(m0 + ty + 16 * i);
        #pragma unroll
        for (int j = 0; j < 4; j++) {
            int n = tx + 16 * j;
            out[m * OUTD + n] = hsum2(acc[i][j]) + __ldg(&bout[n]);
        }
    }
}

// =============================================================
extern "C" void kernel_launch(void* const* d_in, const int* in_sizes, int n_in,
                              void* d_out, int out_size)
{
    (void)in_sizes; (void)n_in; (void)out_size;
    const float* x    = (const float*)d_in[0];
    const float* h0   = (const float*)d_in[1];
    const float* c0   = (const float*)d_in[2];
    const float* Wih  = (const float*)d_in[3];
    const float* Whh  = (const float*)d_in[4];
    const float* b    = (const float*)d_in[5];
    const float* Wout = (const float*)d_in[6];
    const float* bout = (const float*)d_in[7];
    float* out = (float*)d_out;

    const int smB = SM_TOT * 4;             // 198464 B
    const int smC = (64 + 64) * 19 * 16;    // 38912 B

    cudaFuncSetAttribute(k_lstm,     cudaFuncAttributeMaxDynamicSharedMemorySize, smB);
    cudaFuncSetAttribute(k_gemm_out, cudaFuncAttributeMaxDynamicSharedMemorySize, smC);

    k_lstm<<<128, 512, smB>>>(x, h0, c0, Whh, Wih, b);

    k_gemm_out<<<(SEQ * BATCH) / 64, 256, smC>>>(Wout, bout, out);
}